// round 14
// baseline (speedup 1.0000x reference)
#include <cuda_runtime.h>
#include <cuda_bf16.h>
#include <stdint.h>

#define NROWS 8192
#define KDIM  2048
#define NOUT  2048

__device__ __align__(256) uint16_t g_xq[(size_t)NROWS * KDIM]; // bf16 bits
__device__ __align__(256) uint16_t g_wq[(size_t)NOUT * KDIM];  // bf16 bits
__device__ __align__(256) float    g_bq[NOUT];

// ---------------------------------------------------------------------------
// posit(8,1) round-to-nearest quantization (matches the jnp reference).
// ---------------------------------------------------------------------------
__device__ __forceinline__ float posit_q(float x) {
    float ax = fabsf(x);
    if (!(ax > 0.0f)) return 0.0f;
    ax = fminf(fmaxf(ax, 2.44140625e-4f), 4096.0f);      // [2^-12, 2^12]
    int bits = __float_as_int(ax);
    int s = ((bits >> 23) & 0xFF) - 127;
    int k = s >> 1;
    int rlen = (k >= 0) ? (k + 2) : (1 - k);
    int fb = 6 - rlen; fb = fb < 0 ? 0 : fb;
    float m   = __int_as_float((bits & 0x7FFFFF) | 0x3F800000);
    float fs  = __int_as_float((127 + fb) << 23);
    float inv = __int_as_float((127 - fb) << 23);
    float mq = rintf(m * fs) * inv;
    if (mq >= 2.0f) { s += 1; mq = 1.0f; }
    float y = mq * __int_as_float((127 + s) << 23);
    return copysignf(y, x);
}

__device__ __forceinline__ uint32_t pq2(float a, float b) {
    __nv_bfloat162 t = __floats2bfloat162_rn(posit_q(a), posit_q(b));
    return *reinterpret_cast<uint32_t*>(&t);
}

#define X8 ((NROWS * KDIM) / 8)            // 2097152
#define W8 ((NOUT * KDIM) / 8)             // 524288

// Wave-tail K-split: 1024 tiles = 888 full (3 exact waves of 296) + 136 split.
#define FULL_TILES 888
#define SPLIT_TILES 136
#define Z4 (SPLIT_TILES * 16384 / 4)       // 557056 float4 zeros

// Fused quant + zeroing of the split-tile output region.
__global__ void quant_all_kernel(const float* __restrict__ x,
                                 const float* __restrict__ w,
                                 const float* __restrict__ b,
                                 float* __restrict__ out) {
    int i = blockIdx.x * blockDim.x + threadIdx.x;
    if (i < X8) {
        const float4* p = reinterpret_cast<const float4*>(x) + (size_t)i * 2;
        float4 v0 = __ldcs(p), v1 = __ldcs(p + 1);
        uint4 o;
        o.x = pq2(v0.x, v0.y); o.y = pq2(v0.z, v0.w);
        o.z = pq2(v1.x, v1.y); o.w = pq2(v1.z, v1.w);
        reinterpret_cast<uint4*>(g_xq)[i] = o;
    } else if (i < X8 + W8) {
        int j = i - X8;
        const float4* p = reinterpret_cast<const float4*>(w) + (size_t)j * 2;
        float4 v0 = __ldcs(p), v1 = __ldcs(p + 1);
        uint4 o;
        o.x = pq2(v0.x, v0.y); o.y = pq2(v0.z, v0.w);
        o.z = pq2(v1.x, v1.y); o.w = pq2(v1.z, v1.w);
        reinterpret_cast<uint4*>(g_wq)[j] = o;
    } else if (i < X8 + W8 + NOUT) {
        int j = i - X8 - W8;
        g_bq[j] = posit_q(__ldcs(b + j));
    } else if (i < X8 + W8 + NOUT + Z4) {
        int zi = i - X8 - W8 - NOUT;
        int t  = FULL_TILES + (zi >> 12);          // 4096 float4 per tile
        int e  = (zi & 4095) * 4;                  // element within tile
        int r  = e >> 7, c = e & 127;
        int by = t >> 4, bx = t & 15;
        size_t addr = (size_t)(by * 128 + r) * NOUT + bx * 128 + c;
        *reinterpret_cast<float4*>(out + addr) = make_float4(0.f, 0.f, 0.f, 0.f);
    }
}

// ---------------------------------------------------------------------------
// bf16 mma.sync GEMM: out = xq @ wq^T + bq  (M=8192, N=2048, K=2048)
// BM=128 x BN=128, BK=64, STAGES=3, 256 threads (8 warps, 2x4),
// warp tile 64x32, 2 CTAs/SM. Wave-tail fix: last 136 tiles are K-split
// into two half-K CTAs that atomicAdd into a pre-zeroed output region.
// ---------------------------------------------------------------------------
#define BM 128
#define BN 128
#define BK 64
#define STAGES 3
#define KITERS (KDIM / BK)                 // 32
#define A_BYTES (BM * 128)                 // 16 KB
#define B_BYTES (BN * 128)                 // 16 KB
#define STAGE_BYTES (A_BYTES + B_BYTES)    // 32 KB
#define SMEM_DYN (STAGES * STAGE_BYTES + 1024)

__device__ __forceinline__ uint32_t swz(uint32_t row, uint32_t byte) {
    return row * 128u + (byte ^ ((row & 7u) * 16u));
}

__device__ __forceinline__ uint32_t smem_u32(const void* p) {
    uint32_t a;
    asm("{ .reg .u64 t; cvta.to.shared.u64 t, %1; cvt.u32.u64 %0, t; }"
        : "=r"(a) : "l"(p));
    return a;
}

__device__ __forceinline__ void cp16(uint32_t dst, const void* src) {
    asm volatile("cp.async.cg.shared.global [%0], [%1], 16;"
                 :: "r"(dst), "l"(src) : "memory");
}

__device__ __forceinline__ void ldsm4(uint32_t& r0, uint32_t& r1,
                                      uint32_t& r2, uint32_t& r3, uint32_t a) {
    asm volatile("ldmatrix.sync.aligned.m8n8.x4.shared.b16 {%0,%1,%2,%3}, [%4];"
                 : "=r"(r0), "=r"(r1), "=r"(r2), "=r"(r3) : "r"(a));
}

__device__ __forceinline__ void mma16816(float* d, const uint32_t* a,
                                         uint32_t b0, uint32_t b1) {
    asm volatile(
        "mma.sync.aligned.m16n8k16.row.col.f32.bf16.bf16.f32 "
        "{%0,%1,%2,%3}, {%4,%5,%6,%7}, {%8,%9}, {%0,%1,%2,%3};"
        : "+f"(d[0]), "+f"(d[1]), "+f"(d[2]), "+f"(d[3])
        : "r"(a[0]), "r"(a[1]), "r"(a[2]), "r"(a[3]), "r"(b0), "r"(b1));
}

__global__ void __launch_bounds__(256, 2)
gemm_kernel(float* __restrict__ out) {
    extern __shared__ char smem_raw[];
    uint32_t sb = smem_u32(smem_raw);
    sb = (sb + 1023u) & ~1023u;

    // Tile / K-range decode (1D launch order controls wave placement)
    const int bid = blockIdx.x;
    int t, k0, k1, mode;                    // mode: 0 full, 1 half0, 2 half1
    if (bid < FULL_TILES)            { t = bid;               k0 = 0;         k1 = KITERS;     mode = 0; }
    else if (bid < FULL_TILES + SPLIT_TILES)
                                     { t = bid;               k0 = 0;         k1 = KITERS / 2; mode = 1; }
    else                             { t = bid - SPLIT_TILES; k0 = KITERS / 2; k1 = KITERS;    mode = 2; }
    const int n0 = (t & 15) * BN;
    const int m0 = (t >> 4) * BM;

    const int tid  = threadIdx.x;
    const int wid  = tid >> 5, lane = tid & 31;
    const int wm   = wid & 1;        // 2 warps along M (64 rows each)
    const int wn   = wid >> 1;       // 4 warps along N (32 cols each)
    const uint32_t rot = wid & 3;    // per-warp kk rotation

    uint32_t rk[4];
    #pragma unroll
    for (int j = 0; j < 4; j++) rk[j] = ((j + rot) & 3u) * 32u;

    const char* agp = (const char*)g_xq + (size_t)(m0 + (tid >> 1)) * KDIM * 2
                      + (tid & 1) * 64;
    const char* bgp = (const char*)g_wq + (size_t)(n0 + (tid >> 1)) * KDIM * 2
                      + (tid & 1) * 64;

    uint32_t a_sw[4], b_sw[4];
    {
        const uint32_t r  = tid >> 1;
        const uint32_t c0 = (tid & 1) * 64;
        #pragma unroll
        for (int c = 0; c < 4; c++) {
            a_sw[c] = swz(r, c0 + c * 16);
            b_sw[c] = swz(r, c0 + c * 16) + A_BYTES;
        }
    }

    // Prologue: fill stages 0,1 with iterations k0, k0+1
    #pragma unroll
    for (int s = 0; s < STAGES - 1; s++) {
        const uint32_t base = sb + s * STAGE_BYTES;
        const int koff = (k0 + s) * 128;
        #pragma unroll
        for (int c = 0; c < 4; c++) {
            cp16(base + a_sw[c], agp + koff + c * 16);
            cp16(base + b_sw[c], bgp + koff + c * 16);
        }
        asm volatile("cp.async.commit_group;" ::: "memory");
    }

    float acc[4][4][4];
    #pragma unroll
    for (int i = 0; i < 4; i++)
        #pragma unroll
        for (int j = 0; j < 4; j++)
            #pragma unroll
            for (int v = 0; v < 4; v++) acc[i][j][v] = 0.0f;

    const uint32_t a_row_lm  = wm * 64 + (lane & 15);         // + mt*16
    const uint32_t a_byte_lm = (lane >> 4) * 16;              // + rk[kk]
    const uint32_t b_row_lm  = wn * 32 + ((lane >> 4) * 8) + (lane & 7); // +p*16
    const uint32_t b_byte_lm = ((lane >> 3) & 1) * 16;        // + rk[kk]

    int s_rd = 0, s_wr = STAGES - 1;
    for (int it = k0; it < k1; ++it) {
        asm volatile("cp.async.wait_group 1;" ::: "memory");
        __syncthreads();

        const uint32_t ab = sb + s_rd * STAGE_BYTES;
        const uint32_t bb = ab + A_BYTES;
        if (++s_rd == STAGES) s_rd = 0;

        const bool have_next = (it + STAGES - 1 < k1);
        const uint32_t wbase = sb + s_wr * STAGE_BYTES;
        const int wkoff = (it + STAGES - 1) * 128;
        if (++s_wr == STAGES) s_wr = 0;

        // Ping-pong fragment buffers; interleaved stage-head burst
        uint32_t af[2][4], bf[2][8];
        ldsm4(af[0][0], af[0][1], af[0][2], af[0][3],
              ab + swz(a_row_lm, rk[0] + a_byte_lm));
        if (have_next) {
            cp16(wbase + a_sw[0], agp + wkoff);
            cp16(wbase + a_sw[1], agp + wkoff + 16);
        }
        ldsm4(bf[0][0], bf[0][1], bf[0][2], bf[0][3],
              bb + swz(b_row_lm, rk[0] + b_byte_lm));
        if (have_next) {
            cp16(wbase + a_sw[2], agp + wkoff + 32);
            cp16(wbase + a_sw[3], agp + wkoff + 48);
        }
        ldsm4(bf[0][4], bf[0][5], bf[0][6], bf[0][7],
              bb + swz(b_row_lm + 16, rk[0] + b_byte_lm));

        #pragma unroll
        for (int kk = 0; kk < 4; kk++) {
            const int bc = kk & 1, bn_ = bc ^ 1;
            if (have_next)
                cp16(wbase + b_sw[kk], bgp + wkoff + kk * 16);
            #pragma unroll
            for (int mt = 0; mt < 4; mt++) {
                const int g  = kk * 4 + mt;
                const int ac = g & 1, an = ac ^ 1;
                if (mt < 3)
                    ldsm4(af[an][0], af[an][1], af[an][2], af[an][3],
                          ab + swz(a_row_lm + (mt + 1) * 16,
                                   rk[kk] + a_byte_lm));
                else if (kk < 3)
                    ldsm4(af[an][0], af[an][1], af[an][2], af[an][3],
                          ab + swz(a_row_lm, rk[kk + 1] + a_byte_lm));
                if (mt == 0 && kk < 3)
                    ldsm4(bf[bn_][0], bf[bn_][1], bf[bn_][2], bf[bn_][3],
                          bb + swz(b_row_lm, rk[kk + 1] + b_byte_lm));
                if (mt == 1 && kk < 3)
                    ldsm4(bf[bn_][4], bf[bn_][5], bf[bn_][6], bf[bn_][7],
                          bb + swz(b_row_lm + 16, rk[kk + 1] + b_byte_lm));
                mma16816(acc[mt][0], af[ac], bf[bc][0], bf[bc][1]);
                mma16816(acc[mt][1], af[ac], bf[bc][2], bf[bc][3]);
                mma16816(acc[mt][2], af[ac], bf[bc][4], bf[bc][5]);
                mma16816(acc[mt][3], af[ac], bf[bc][6], bf[bc][7]);
            }
        }
        asm volatile("cp.async.commit_group;" ::: "memory");
    }

    // Epilogue
    const int ncol = n0 + wn * 32 + (lane & 3) * 2;
    const int mrow = m0 + wm * 64 + (lane >> 2);
    const bool addb = (mode <= 1);          // full or half0 add bias

    float2 bv[4];
    #pragma unroll
    for (int nt = 0; nt < 4; nt++) {
        float2 v = *reinterpret_cast<const float2*>(&g_bq[ncol + nt * 8]);
        bv[nt] = addb ? v : make_float2(0.f, 0.f);
    }

    #pragma unroll
    for (int mt = 0; mt < 4; mt++) {
        float* r0 = out + (size_t)(mrow + mt * 16) * NOUT;
        float* r1 = r0 + 8 * NOUT;
        #pragma unroll
        for (int nt = 0; nt < 4; nt++) {
            float l0 = acc[mt][nt][0] + bv[nt].x;
            float l1 = acc[mt][nt][1] + bv[nt].y;
            float h0 = acc[mt][nt][2] + bv[nt].x;
            float h1 = acc[mt][nt][3] + bv[nt].y;
            float* p0 = r0 + ncol + nt * 8;
            float* p1 = r1 + ncol + nt * 8;
            if (mode == 0) {
                __stcs(reinterpret_cast<float2*>(p0), make_float2(l0, l1));
                __stcs(reinterpret_cast<float2*>(p1), make_float2(h0, h1));
            } else {
                atomicAdd(p0, l0); atomicAdd(p0 + 1, l1);
                atomicAdd(p1, h0); atomicAdd(p1 + 1, h1);
            }
        }
    }
}

// ---------------------------------------------------------------------------
extern "C" void kernel_launch(void* const* d_in, const int* in_sizes, int n_in,
                              void* d_out, int out_size) {
    const float* x = nullptr; const float* w = nullptr; const float* b = nullptr;
    for (int i = 0; i < n_in; i++) {
        if (in_sizes[i] == NROWS * KDIM)      x = (const float*)d_in[i];
        else if (in_sizes[i] == NOUT * KDIM)  w = (const float*)d_in[i];
        else if (in_sizes[i] == NOUT)         b = (const float*)d_in[i];
    }

    {
        int total = X8 + W8 + NOUT + Z4;
        quant_all_kernel<<<(total + 511) / 512, 512>>>(x, w, b, (float*)d_out);
    }

    cudaFuncSetAttribute(gemm_kernel,
                         cudaFuncAttributeMaxDynamicSharedMemorySize, SMEM_DYN);
    // 888 full-K tiles + 136 x 2 half-K tiles, launched in wave order
    gemm_kernel<<<FULL_TILES + 2 * SPLIT_TILES, 256, SMEM_DYN>>>((float*)d_out);
}

// round 15
// speedup vs baseline: 1.0780x; 1.0780x over previous
#include <cuda_runtime.h>
#include <cuda_bf16.h>
#include <stdint.h>

#define NROWS 8192
#define KDIM  2048
#define NOUT  2048

__device__ __align__(256) uint16_t g_xq[(size_t)NROWS * KDIM]; // bf16 bits
__device__ __align__(256) uint16_t g_wq[(size_t)NOUT * KDIM];  // bf16 bits
__device__ __align__(256) float    g_bq[NOUT];

// ---------------------------------------------------------------------------
// posit(8,1) round-to-nearest quantization (matches the jnp reference).
// ---------------------------------------------------------------------------
__device__ __forceinline__ float posit_q(float x) {
    float ax = fabsf(x);
    if (!(ax > 0.0f)) return 0.0f;
    ax = fminf(fmaxf(ax, 2.44140625e-4f), 4096.0f);      // [2^-12, 2^12]
    int bits = __float_as_int(ax);
    int s = ((bits >> 23) & 0xFF) - 127;
    int k = s >> 1;
    int rlen = (k >= 0) ? (k + 2) : (1 - k);
    int fb = 6 - rlen; fb = fb < 0 ? 0 : fb;
    float m   = __int_as_float((bits & 0x7FFFFF) | 0x3F800000);
    float fs  = __int_as_float((127 + fb) << 23);
    float inv = __int_as_float((127 - fb) << 23);
    float mq = rintf(m * fs) * inv;
    if (mq >= 2.0f) { s += 1; mq = 1.0f; }
    float y = mq * __int_as_float((127 + s) << 23);
    return copysignf(y, x);
}

__device__ __forceinline__ uint32_t pq2(float a, float b) {
    __nv_bfloat162 t = __floats2bfloat162_rn(posit_q(a), posit_q(b));
    return *reinterpret_cast<uint32_t*>(&t);
}

#define X16 ((NROWS * KDIM) / 16)          // 1048576
#define W16 ((NOUT * KDIM) / 16)           // 262144

__device__ __forceinline__ void quant16(const float* __restrict__ src,
                                        uint16_t* __restrict__ dst, int i) {
    const float4* p = reinterpret_cast<const float4*>(src) + (size_t)i * 4;
    float4 v0 = __ldcs(p), v1 = __ldcs(p + 1);
    float4 v2 = __ldcs(p + 2), v3 = __ldcs(p + 3);
    uint4 o0, o1;
    o0.x = pq2(v0.x, v0.y); o0.y = pq2(v0.z, v0.w);
    o0.z = pq2(v1.x, v1.y); o0.w = pq2(v1.z, v1.w);
    o1.x = pq2(v2.x, v2.y); o1.y = pq2(v2.z, v2.w);
    o1.z = pq2(v3.x, v3.y); o1.w = pq2(v3.z, v3.w);
    uint4* q = reinterpret_cast<uint4*>(dst) + (size_t)i * 2;
    q[0] = o0;
    q[1] = o1;
}

// Fused quant: 16 floats/thread for x and w, scalar for bias.
__global__ void quant_all_kernel(const float* __restrict__ x,
                                 const float* __restrict__ w,
                                 const float* __restrict__ b) {
    int i = blockIdx.x * blockDim.x + threadIdx.x;
    if (i < X16) {
        quant16(x, g_xq, i);
    } else if (i < X16 + W16) {
        quant16(w, g_wq, i - X16);
    } else if (i < X16 + W16 + NOUT) {
        int j = i - X16 - W16;
        g_bq[j] = posit_q(__ldcs(b + j));
    }
}

// ---------------------------------------------------------------------------
// bf16 mma.sync GEMM: out = xq @ wq^T + bq  (M=8192, N=2048, K=2048)
// BM=128 x BN=128, BK=64, STAGES=3, 256 threads (8 warps, 2x4),
// warp tile 64x32, 2 CTAs/SM. De-phasing: per-warp kk rotation,
// cp.async spread over kk loop, B prefetch split over mt=0/1,
// interleaved stage-head burst. Streaming epilogue stores.
// (Validated plateau config — R13.)
// ---------------------------------------------------------------------------
#define BM 128
#define BN 128
#define BK 64
#define STAGES 3
#define KITERS (KDIM / BK)                 // 32
#define A_BYTES (BM * 128)                 // 16 KB
#define B_BYTES (BN * 128)                 // 16 KB
#define STAGE_BYTES (A_BYTES + B_BYTES)    // 32 KB
#define SMEM_DYN (STAGES * STAGE_BYTES + 1024)

__device__ __forceinline__ uint32_t swz(uint32_t row, uint32_t byte) {
    return row * 128u + (byte ^ ((row & 7u) * 16u));
}

__device__ __forceinline__ uint32_t smem_u32(const void* p) {
    uint32_t a;
    asm("{ .reg .u64 t; cvta.to.shared.u64 t, %1; cvt.u32.u64 %0, t; }"
        : "=r"(a) : "l"(p));
    return a;
}

__device__ __forceinline__ void cp16(uint32_t dst, const void* src) {
    asm volatile("cp.async.cg.shared.global [%0], [%1], 16;"
                 :: "r"(dst), "l"(src) : "memory");
}

__device__ __forceinline__ void ldsm4(uint32_t& r0, uint32_t& r1,
                                      uint32_t& r2, uint32_t& r3, uint32_t a) {
    asm volatile("ldmatrix.sync.aligned.m8n8.x4.shared.b16 {%0,%1,%2,%3}, [%4];"
                 : "=r"(r0), "=r"(r1), "=r"(r2), "=r"(r3) : "r"(a));
}

__device__ __forceinline__ void mma16816(float* d, const uint32_t* a,
                                         uint32_t b0, uint32_t b1) {
    asm volatile(
        "mma.sync.aligned.m16n8k16.row.col.f32.bf16.bf16.f32 "
        "{%0,%1,%2,%3}, {%4,%5,%6,%7}, {%8,%9}, {%0,%1,%2,%3};"
        : "+f"(d[0]), "+f"(d[1]), "+f"(d[2]), "+f"(d[3])
        : "r"(a[0]), "r"(a[1]), "r"(a[2]), "r"(a[3]), "r"(b0), "r"(b1));
}

__global__ void __launch_bounds__(256, 2)
gemm_kernel(float* __restrict__ out) {
    extern __shared__ char smem_raw[];
    uint32_t sb = smem_u32(smem_raw);
    sb = (sb + 1023u) & ~1023u;

    const int tid  = threadIdx.x;
    const int wid  = tid >> 5, lane = tid & 31;
    const int wm   = wid & 1;        // 2 warps along M (64 rows each)
    const int wn   = wid >> 1;       // 4 warps along N (32 cols each)
    const int n0   = blockIdx.x * BN;
    const int m0   = blockIdx.y * BM;
    const uint32_t rot = wid & 3;    // per-warp kk rotation

    uint32_t rk[4];
    #pragma unroll
    for (int j = 0; j < 4; j++) rk[j] = ((j + rot) & 3u) * 32u;

    const char* agp = (const char*)g_xq + (size_t)(m0 + (tid >> 1)) * KDIM * 2
                      + (tid & 1) * 64;
    const char* bgp = (const char*)g_wq + (size_t)(n0 + (tid >> 1)) * KDIM * 2
                      + (tid & 1) * 64;

    uint32_t a_sw[4], b_sw[4];
    {
        const uint32_t r  = tid >> 1;
        const uint32_t c0 = (tid & 1) * 64;
        #pragma unroll
        for (int c = 0; c < 4; c++) {
            a_sw[c] = swz(r, c0 + c * 16);
            b_sw[c] = swz(r, c0 + c * 16) + A_BYTES;
        }
    }

    // Prologue: fill stages 0,1
    #pragma unroll
    for (int s = 0; s < STAGES - 1; s++) {
        const uint32_t base = sb + s * STAGE_BYTES;
        const int koff = s * 128;
        #pragma unroll
        for (int c = 0; c < 4; c++) {
            cp16(base + a_sw[c], agp + koff + c * 16);
            cp16(base + b_sw[c], bgp + koff + c * 16);
        }
        asm volatile("cp.async.commit_group;" ::: "memory");
    }

    float acc[4][4][4];
    #pragma unroll
    for (int i = 0; i < 4; i++)
        #pragma unroll
        for (int j = 0; j < 4; j++)
            #pragma unroll
            for (int v = 0; v < 4; v++) acc[i][j][v] = 0.0f;

    const uint32_t a_row_lm  = wm * 64 + (lane & 15);         // + mt*16
    const uint32_t a_byte_lm = (lane >> 4) * 16;              // + rk[kk]
    const uint32_t b_row_lm  = wn * 32 + ((lane >> 4) * 8) + (lane & 7); // +p*16
    const uint32_t b_byte_lm = ((lane >> 3) & 1) * 16;        // + rk[kk]

    int s_rd = 0, s_wr = STAGES - 1;
    for (int it = 0; it < KITERS; ++it) {
        asm volatile("cp.async.wait_group 1;" ::: "memory");
        __syncthreads();

        const uint32_t ab = sb + s_rd * STAGE_BYTES;
        const uint32_t bb = ab + A_BYTES;
        if (++s_rd == STAGES) s_rd = 0;

        const bool have_next = (it + STAGES - 1 < KITERS);
        const uint32_t wbase = sb + s_wr * STAGE_BYTES;
        const int wkoff = (it + STAGES - 1) * 128;
        if (++s_wr == STAGES) s_wr = 0;

        // Ping-pong fragment buffers; interleaved stage-head burst
        uint32_t af[2][4], bf[2][8];
        ldsm4(af[0][0], af[0][1], af[0][2], af[0][3],
              ab + swz(a_row_lm, rk[0] + a_byte_lm));
        if (have_next) {
            cp16(wbase + a_sw[0], agp + wkoff);
            cp16(wbase + a_sw[1], agp + wkoff + 16);
        }
        ldsm4(bf[0][0], bf[0][1], bf[0][2], bf[0][3],
              bb + swz(b_row_lm, rk[0] + b_byte_lm));
        if (have_next) {
            cp16(wbase + a_sw[2], agp + wkoff + 32);
            cp16(wbase + a_sw[3], agp + wkoff + 48);
        }
        ldsm4(bf[0][4], bf[0][5], bf[0][6], bf[0][7],
              bb + swz(b_row_lm + 16, rk[0] + b_byte_lm));

        #pragma unroll
        for (int kk = 0; kk < 4; kk++) {
            const int bc = kk & 1, bn_ = bc ^ 1;
            // One B chunk cp16 per kk boundary (smoothed LSU pressure)
            if (have_next)
                cp16(wbase + b_sw[kk], bgp + wkoff + kk * 16);
            #pragma unroll
            for (int mt = 0; mt < 4; mt++) {
                const int g  = kk * 4 + mt;
                const int ac = g & 1, an = ac ^ 1;
                // Prefetch next A fragment (next mt, or next kk's mt=0)
                if (mt < 3)
                    ldsm4(af[an][0], af[an][1], af[an][2], af[an][3],
                          ab + swz(a_row_lm + (mt + 1) * 16,
                                   rk[kk] + a_byte_lm));
                else if (kk < 3)
                    ldsm4(af[an][0], af[an][1], af[an][2], af[an][3],
                          ab + swz(a_row_lm, rk[kk + 1] + a_byte_lm));
                // Next kk's B pair: one half at mt=0, other at mt=1
                if (mt == 0 && kk < 3)
                    ldsm4(bf[bn_][0], bf[bn_][1], bf[bn_][2], bf[bn_][3],
                          bb + swz(b_row_lm, rk[kk + 1] + b_byte_lm));
                if (mt == 1 && kk < 3)
                    ldsm4(bf[bn_][4], bf[bn_][5], bf[bn_][6], bf[bn_][7],
                          bb + swz(b_row_lm + 16, rk[kk + 1] + b_byte_lm));
                mma16816(acc[mt][0], af[ac], bf[bc][0], bf[bc][1]);
                mma16816(acc[mt][1], af[ac], bf[bc][2], bf[bc][3]);
                mma16816(acc[mt][2], af[ac], bf[bc][4], bf[bc][5]);
                mma16816(acc[mt][3], af[ac], bf[bc][6], bf[bc][7]);
            }
        }
        asm volatile("cp.async.commit_group;" ::: "memory");
    }

    // Epilogue: streaming float2 stores + bias (out is never re-read)
    const int ncol = n0 + wn * 32 + (lane & 3) * 2;
    float2 bv[4];
    #pragma unroll
    for (int nt = 0; nt < 4; nt++)
        bv[nt] = *reinterpret_cast<const float2*>(&g_bq[ncol + nt * 8]);

    const int mrow = m0 + wm * 64 + (lane >> 2);
    #pragma unroll
    for (int mt = 0; mt < 4; mt++) {
        float* r0 = out + (size_t)(mrow + mt * 16) * NOUT;
        float* r1 = r0 + 8 * NOUT;
        #pragma unroll
        for (int nt = 0; nt < 4; nt++) {
            float2 lo = make_float2(acc[mt][nt][0] + bv[nt].x,
                                    acc[mt][nt][1] + bv[nt].y);
            float2 hi = make_float2(acc[mt][nt][2] + bv[nt].x,
                                    acc[mt][nt][3] + bv[nt].y);
            __stcs(reinterpret_cast<float2*>(r0 + ncol + nt * 8), lo);
            __stcs(reinterpret_cast<float2*>(r1 + ncol + nt * 8), hi);
        }
    }
}

// ---------------------------------------------------------------------------
extern "C" void kernel_launch(void* const* d_in, const int* in_sizes, int n_in,
                              void* d_out, int out_size) {
    const float* x = nullptr; const float* w = nullptr; const float* b = nullptr;
    for (int i = 0; i < n_in; i++) {
        if (in_sizes[i] == NROWS * KDIM)      x = (const float*)d_in[i];
        else if (in_sizes[i] == NOUT * KDIM)  w = (const float*)d_in[i];
        else if (in_sizes[i] == NOUT)         b = (const float*)d_in[i];
    }

    {
        int total = X16 + W16 + NOUT;
        quant_all_kernel<<<(total + 255) / 256, 256>>>(x, w, b);
    }

    cudaFuncSetAttribute(gemm_kernel,
                         cudaFuncAttributeMaxDynamicSharedMemorySize, SMEM_DYN);
    dim3 grid(NOUT / BN, NROWS / BM);   // (16, 64)
    gemm_kernel<<<grid, 256, SMEM_DYN>>>((float*)d_out);
}